// round 2
// baseline (speedup 1.0000x reference)
#include <cuda_runtime.h>
#include <cuda_bf16.h>

#define N_RAYS 65536
#define N_PTS  128
#define WARPS_PER_BLOCK 8

__global__ __launch_bounds__(32 * WARPS_PER_BLOCK)
void volrend_kernel(const float* __restrict__ density,
                    const float* __restrict__ feature,
                    const float* __restrict__ depth,
                    float* __restrict__ out)
{
    const unsigned FULL = 0xffffffffu;
    int lane = threadIdx.x & 31;
    int ray  = blockIdx.x * WARPS_PER_BLOCK + (threadIdx.x >> 5);
    if (ray >= N_RAYS) return;

    // ---- coalesced float4 loads: lane l owns samples [4l, 4l+3] ----
    const float4* dep4 = reinterpret_cast<const float4*>(depth   + (size_t)ray * N_PTS);
    const float4* den4 = reinterpret_cast<const float4*>(density + (size_t)ray * N_PTS);
    float4 dp = dep4[lane];
    float4 dn = den4[lane];

    // feature: 12 consecutive floats per lane (3x float4, covers ray contiguously)
    const float4* f4 = reinterpret_cast<const float4*>(feature + (size_t)ray * (N_PTS * 3)) + lane * 3;
    float4 f0 = f4[0];
    float4 f1 = f4[1];
    float4 f2 = f4[2];

    // ---- deltas (boundary sample from next lane; lane31 last = 1e10) ----
    float nxt = __shfl_down_sync(FULL, dp.x, 1);
    float dv[4]    = { dp.x, dp.y, dp.z, dp.w };
    float dens[4]  = { dn.x, dn.y, dn.z, dn.w };
    float delta[4];
    delta[0] = dp.y - dp.x;
    delta[1] = dp.z - dp.y;
    delta[2] = dp.w - dp.z;
    delta[3] = (lane == 31) ? 1e10f : (nxt - dp.w);

    // ---- alpha and (1 - alpha + eps) = exp(-delta*sigma) + eps ----
    float alpha[4], a[4];
    #pragma unroll
    for (int k = 0; k < 4; k++) {
        float e  = __expf(-delta[k] * dens[k]);
        alpha[k] = 1.0f - e;
        a[k]     = e + 1e-10f;
    }

    // ---- local exclusive prefix products within the lane's 4 samples ----
    float lp[4];
    lp[0] = 1.0f;
    lp[1] = a[0];
    lp[2] = lp[1] * a[1];
    lp[3] = lp[2] * a[2];
    float lane_prod = lp[3] * a[3];

    // ---- warp inclusive scan (product) over lane products ----
    float scan = lane_prod;
    #pragma unroll
    for (int d = 1; d < 32; d <<= 1) {
        float v = __shfl_up_sync(FULL, scan, d);
        if (lane >= d) scan *= v;
    }
    float excl = __shfl_up_sync(FULL, scan, 1);
    if (lane == 0) excl = 1.0f;

    // ---- unpack features per sample ----
    float fr[4] = { f0.x, f0.w, f1.z, f2.y };
    float fg[4] = { f0.y, f1.x, f1.w, f2.z };
    float fb[4] = { f0.z, f1.y, f2.x, f2.w };

    // ---- weighted accumulation ----
    float r = 0.f, g = 0.f, b = 0.f, ds = 0.f;
    #pragma unroll
    for (int k = 0; k < 4; k++) {
        float w = excl * lp[k] * alpha[k];
        r  += w * fr[k];
        g  += w * fg[k];
        b  += w * fb[k];
        ds += w * dv[k];
    }

    // ---- warp butterfly reduction ----
    #pragma unroll
    for (int off = 16; off; off >>= 1) {
        r  += __shfl_xor_sync(FULL, r,  off);
        g  += __shfl_xor_sync(FULL, g,  off);
        b  += __shfl_xor_sync(FULL, b,  off);
        ds += __shfl_xor_sync(FULL, ds, off);
    }

    if (lane == 0) {
        float* rgb = out + (size_t)ray * 3;
        rgb[0] = r; rgb[1] = g; rgb[2] = b;
        float* dout = out + (size_t)N_RAYS * 3 + (size_t)ray * 3;
        dout[0] = ds; dout[1] = ds; dout[2] = ds;
    }
}

extern "C" void kernel_launch(void* const* d_in, const int* in_sizes, int n_in,
                              void* d_out, int out_size)
{
    const float* density = (const float*)d_in[0];
    const float* feature = (const float*)d_in[1];
    const float* depth   = (const float*)d_in[2];
    float* out = (float*)d_out;

    int blocks = N_RAYS / WARPS_PER_BLOCK;  // 8192
    volrend_kernel<<<blocks, 32 * WARPS_PER_BLOCK>>>(density, feature, depth, out);
}